// round 3
// baseline (speedup 1.0000x reference)
#include <cuda_runtime.h>
#include <cuda_bf16.h>
#include <cstdint>

// ---------------------------------------------------------------------------
// HGNN layer:
//   x1   = x @ W1                        [N,256]
//   edge = relu( SW @ x1 )               [E,256]   (SW: uniform weights over seq slots with id>0)
//   e1   = edge @ W2                     [E,256]
//   node = UW @ e1                       [N,256]   (UW: uniform weights over useq slots with id>0)
// N=50000, E=25000, L=32, IN=OUT=256, fp32.
// ---------------------------------------------------------------------------

#define N_NODES 50000
#define N_EDGES 25000
#define DIM     256
#define LW      32

// Scratch (no allocations allowed). Kernels reference these symbols directly —
// kernel_launch makes no runtime API calls other than kernel launches.
__device__ float g_x1[N_NODES * DIM];
__device__ float g_edge[N_EDGES * DIM];
__device__ float g_e1[N_EDGES * DIM];

// ---------------------------------------------------------------------------
// SGEMM: C[M,256] = A[M,256] @ B[256,256], all row-major fp32.
// BM=128, BN=128, BK=8, 256 threads, 8x8 per thread.
// FIRST=true:  A = x (param),   C = g_x1
// FIRST=false: A = g_edge,      C = g_e1
// ---------------------------------------------------------------------------
#define BM 128
#define BN 128
#define BK 8
#define TM 8
#define TN 8

template <bool FIRST>
__global__ __launch_bounds__(256, 2)
void sgemm_256(const float* __restrict__ Aext, const float* __restrict__ B, int M)
{
    const float* __restrict__ A = FIRST ? Aext : (const float*)g_edge;
    float* __restrict__ C       = FIRST ? g_x1 : g_e1;

    const int K  = DIM;
    const int Nc = DIM;

    __shared__ float As[BK][BM];       // transposed A tile
    __shared__ float Bs[BK][BN];

    const int tid  = threadIdx.x;
    const int brow = blockIdx.x * BM;
    const int bcol = blockIdx.y * BN;

    // A tile load map: 128 rows x 8 cols -> 2 float4 per row, 256 threads
    const int a_row  = tid >> 1;           // 0..127
    const int a_col4 = (tid & 1) * 4;      // 0 or 4
    // B tile load map: 8 rows x 128 cols -> 32 float4 per row
    const int b_row  = tid >> 5;           // 0..7
    const int b_col4 = (tid & 31) * 4;     // 0..124

    const int ty = (tid >> 4) * TM;        // 0..120
    const int tx = (tid & 15) * TN;        // 0..120

    float acc[TM][TN];
#pragma unroll
    for (int i = 0; i < TM; i++)
#pragma unroll
        for (int j = 0; j < TN; j++) acc[i][j] = 0.f;

    for (int k0 = 0; k0 < K; k0 += BK) {
        // load A tile (guard M edge)
        float4 av = make_float4(0.f, 0.f, 0.f, 0.f);
        const int gr = brow + a_row;
        if (gr < M)
            av = *reinterpret_cast<const float4*>(&A[(size_t)gr * K + k0 + a_col4]);
        As[a_col4 + 0][a_row] = av.x;
        As[a_col4 + 1][a_row] = av.y;
        As[a_col4 + 2][a_row] = av.z;
        As[a_col4 + 3][a_row] = av.w;

        // load B tile (always in range: K=Nc=256)
        float4 bv = *reinterpret_cast<const float4*>(&B[(size_t)(k0 + b_row) * Nc + bcol + b_col4]);
        *reinterpret_cast<float4*>(&Bs[b_row][b_col4]) = bv;

        __syncthreads();

#pragma unroll
        for (int kk = 0; kk < BK; kk++) {
            float ar[TM], br[TN];
#pragma unroll
            for (int i = 0; i < TM; i++) ar[i] = As[kk][ty + i];
#pragma unroll
            for (int j = 0; j < TN; j++) br[j] = Bs[kk][tx + j];
#pragma unroll
            for (int i = 0; i < TM; i++)
#pragma unroll
                for (int j = 0; j < TN; j++)
                    acc[i][j] = fmaf(ar[i], br[j], acc[i][j]);
        }
        __syncthreads();
    }

    // store
#pragma unroll
    for (int i = 0; i < TM; i++) {
        const int row = brow + ty + i;
        if (row < M) {
            float* cp = &C[(size_t)row * Nc + bcol + tx];
            *reinterpret_cast<float4*>(cp + 0) =
                make_float4(acc[i][0], acc[i][1], acc[i][2], acc[i][3]);
            *reinterpret_cast<float4*>(cp + 4) =
                make_float4(acc[i][4], acc[i][5], acc[i][6], acc[i][7]);
        }
    }
}

// ---------------------------------------------------------------------------
// Gather + uniform-weight reduce.
//   out[r] = scale * sum_{l: valid} src[idx[r][l]]     (scale = 1/cnt; if cnt==0
//                                                       all 32 slots count, scale = 1/32)
// 4 rows per 256-thread block; 64 threads per row, one float4 lane each.
// EDGE=true:  src = g_x1, out = g_edge, fused relu.
// EDGE=false: src = g_e1, out = param (d_out).
// ---------------------------------------------------------------------------
template <bool EDGE>
__global__ __launch_bounds__(256)
void gather_reduce(const int* __restrict__ idx, float4* __restrict__ out_ext, int rows)
{
    const float4* __restrict__ src = EDGE ? (const float4*)g_x1 : (const float4*)g_e1;
    float4* __restrict__ out       = EDGE ? (float4*)g_edge : out_ext;

    __shared__ int sidx[4][LW];

    const int tid = threadIdx.x;
    const int r0  = blockIdx.x * 4;

    if (tid < 4 * LW) {
        const int r = r0 + (tid >> 5);
        const int l = tid & 31;
        sidx[tid >> 5][l] = (r < rows) ? idx[(size_t)r * LW + l] : 0;
    }
    __syncthreads();

    const int g    = tid >> 6;      // 0..3  (row within block)
    const int lane = tid & 63;      // float4 lane (0..63 -> 256 floats)
    const int r    = r0 + g;
    if (r >= rows) return;

    const int* ids = sidx[g];

    int cnt = 0;
#pragma unroll
    for (int l = 0; l < LW; l++) cnt += (ids[l] > 0);

    const bool all = (cnt == 0);

    float4 acc0 = make_float4(0.f, 0.f, 0.f, 0.f);
    float4 acc1 = make_float4(0.f, 0.f, 0.f, 0.f);
#pragma unroll
    for (int l = 0; l < LW; l += 2) {
        const int id0 = ids[l];
        const int id1 = ids[l + 1];
        if (all || id0 > 0) {
            const float4 v = __ldg(&src[(size_t)id0 * 64 + lane]);
            acc0.x += v.x; acc0.y += v.y; acc0.z += v.z; acc0.w += v.w;
        }
        if (all || id1 > 0) {
            const float4 v = __ldg(&src[(size_t)id1 * 64 + lane]);
            acc1.x += v.x; acc1.y += v.y; acc1.z += v.z; acc1.w += v.w;
        }
    }

    const float s = (cnt > 0) ? (1.f / (float)cnt) : (1.f / (float)LW);
    float4 o;
    o.x = (acc0.x + acc1.x) * s;
    o.y = (acc0.y + acc1.y) * s;
    o.z = (acc0.z + acc1.z) * s;
    o.w = (acc0.w + acc1.w) * s;
    if (EDGE) {
        o.x = fmaxf(o.x, 0.f);
        o.y = fmaxf(o.y, 0.f);
        o.z = fmaxf(o.z, 0.f);
        o.w = fmaxf(o.w, 0.f);
    }
    out[(size_t)r * 64 + lane] = o;
}

// ---------------------------------------------------------------------------
// Launch — kernel launches ONLY (graph-capture safe).
// ---------------------------------------------------------------------------
extern "C" void kernel_launch(void* const* d_in, const int* in_sizes, int n_in,
                              void* d_out, int out_size)
{
    const float* x    = (const float*)d_in[0];   // [N,256]
    const int*   seq  = (const int*)  d_in[1];   // [E,32]
    const int*   useq = (const int*)  d_in[2];   // [N,32]
    const float* W1   = (const float*)d_in[3];   // [256,256]
    const float* W2   = (const float*)d_in[4];   // [256,256]
    float*       out  = (float*)d_out;           // [N,256]

    int N = in_sizes[2] / LW;   // useq is [N,32]
    int E = in_sizes[1] / LW;   // seq  is [E,32]
    if (N <= 0 || N > N_NODES) N = N_NODES;     // defensive fallback only
    if (E <= 0 || E > N_EDGES) E = N_EDGES;

    // 1) x1 = x @ W1
    {
        dim3 grid((N + BM - 1) / BM, DIM / BN);
        sgemm_256<true><<<grid, 256>>>(x, W1, N);
    }
    // 2) edge = relu(gather(x1, seq))
    {
        dim3 grid((E + 3) / 4);
        gather_reduce<true><<<grid, 256>>>(seq, nullptr, E);
    }
    // 3) e1 = edge @ W2
    {
        dim3 grid((E + BM - 1) / BM, DIM / BN);
        sgemm_256<false><<<grid, 256>>>(nullptr, W2, E);
    }
    // 4) node = gather(e1, useq)  -> d_out
    {
        dim3 grid((N + 3) / 4);
        gather_reduce<false><<<grid, 256>>>(useq, (float4*)out, N);
    }
}

// round 11
// speedup vs baseline: 2.5038x; 2.5038x over previous
#include <cuda_runtime.h>
#include <cuda_fp16.h>
#include <cstdint>

// ===========================================================================
// HGNN layer on GB300 (sm_103a harness, compiled to generic sm_103 target):
//   x1   = x @ W1      (mma.sync tf32 tensor cores, fp16 output)   [N,256]
//   edge = relu(gatherAvg(x1, seq))    (fp16 gather, fp32 out)     [E,256]
//   e1   = edge @ W2   (mma.sync tf32 tensor cores, fp16 output)   [E,256]
//   node = gatherAvg(e1, useq)         (fp16 gather, fp32 out)     [N,256]
// tcgen05 is unavailable (ptxas targets sm_103 without the 'a' features),
// so GEMMs use arch-generic mma.sync.m16n8k8 tf32.
// ===========================================================================

#define N_NODES 50000
#define N_EDGES 25000
#define DIM     256
#define LW      32

// Scratch (static __device__; no allocations anywhere).
__device__ __half g_x1[N_NODES * DIM];     // 25.6 MB
__device__ float  g_edge[N_EDGES * DIM];   // 25.6 MB
__device__ __half g_e1[N_EDGES * DIM];     // 12.8 MB

// ---------------------------------------------------------------------------
// tf32 helpers
// ---------------------------------------------------------------------------
__device__ __forceinline__ uint32_t f2tf32(float f) {
    uint32_t r;
    asm("cvt.rna.tf32.f32 %0, %1;" : "=r"(r) : "f"(f));
    return r;
}

__device__ __forceinline__ void mma_tf32(float& c0, float& c1, float& c2, float& c3,
                                         uint32_t a0, uint32_t a1, uint32_t a2, uint32_t a3,
                                         uint32_t b0, uint32_t b1)
{
    asm volatile(
        "mma.sync.aligned.m16n8k8.row.col.f32.tf32.tf32.f32 "
        "{%0,%1,%2,%3}, {%4,%5,%6,%7}, {%8,%9}, {%0,%1,%2,%3};"
        : "+f"(c0), "+f"(c1), "+f"(c2), "+f"(c3)
        : "r"(a0), "r"(a1), "r"(a2), "r"(a3), "r"(b0), "r"(b1));
}

// ---------------------------------------------------------------------------
// Persistent tensor-core GEMM:
//   C[M,256](fp16) = A[M,256](fp32 -> tf32 rna) @ W[256,256](fp32 -> tf32 rna)
//
// Grid (148, 2): blockIdx.y selects a 128-wide N half. Each CTA loads its
// W-half into smem ONCE (256x128 tf32, padded stride 136 -> conflict-free),
// then loops persistently over 128-row M tiles with double-buffered A chunks
// (128x32, padded stride 36 -> conflict-free).
//
// 256 threads = 8 warps in a 4(M) x 2(N) grid; warp tile 32x64:
//   2 m-frags (m16) x 8 n-frags (n8), K in 8 chunks of 32 (4 k8-steps each).
//
// FIRST=true:  A = x (param),  C = g_x1
// FIRST=false: A = g_edge,     C = g_e1
// ---------------------------------------------------------------------------
#define BM     128
#define BNH    128            // N per blockIdx.y half
#define KC     32             // K chunk
#define BSTR   136            // B smem row stride (words): bank-conflict-free
#define ASTR   36             // A smem row stride (words): bank-conflict-free
#define B_WORDS (DIM * BSTR)              // 34816
#define A_WORDS (BM * ASTR)               // 4608
#define GEMM_SMEM_BYTES ((B_WORDS + 2 * A_WORDS) * 4)   // 176128 B

template <bool FIRST>
__global__ __launch_bounds__(256, 1)
void gemm_mma(const float* __restrict__ Aext, const float* __restrict__ W, int M)
{
    const float* __restrict__ A = FIRST ? Aext : g_edge;
    __half* __restrict__      C = FIRST ? g_x1 : g_e1;

    extern __shared__ uint32_t sm[];
    uint32_t* Bs = sm;                       // [256][BSTR]
    uint32_t* As = sm + B_WORDS;             // [2][128][ASTR]

    const int tid  = threadIdx.x;
    const int lane = tid & 31;
    const int wid  = tid >> 5;
    const int wm   = wid >> 1;               // 0..3 -> rows wm*32
    const int wn   = wid & 1;                // 0..1 -> cols wn*64
    const int g    = lane >> 2;              // 0..7
    const int t    = lane & 3;               // 0..3
    const int nhalf = blockIdx.y;            // 0/1

    // ---- Load W half into smem (once), converting to tf32 (rna) ----
    // 256 rows x 128 cols -> 8192 float4, 32 per thread.
#pragma unroll 8
    for (int i = 0; i < 32; i++) {
        const int f   = tid + 256 * i;
        const int row = f >> 5;              // k: 0..255
        const int q   = f & 31;              // col4: 0..31
        const float4 v = *reinterpret_cast<const float4*>(
            &W[(size_t)row * DIM + nhalf * BNH + q * 4]);
        uint4 u = make_uint4(f2tf32(v.x), f2tf32(v.y), f2tf32(v.z), f2tf32(v.w));
        *reinterpret_cast<uint4*>(&Bs[row * BSTR + q * 4]) = u;
    }

    const int numTiles = (M + BM - 1) / BM;

    for (int tile = blockIdx.x; tile < numTiles; tile += gridDim.x) {
        const int m0 = tile * BM;

        float c[2][8][4];
#pragma unroll
        for (int mf = 0; mf < 2; mf++)
#pragma unroll
            for (int nf = 0; nf < 8; nf++)
#pragma unroll
                for (int j = 0; j < 4; j++) c[mf][nf][j] = 0.f;

        // ---- prologue: chunk 0 -> buf 0 ----
        {
            __syncthreads();   // previous tile fully done before overwriting A smem
            float4 av[4];
#pragma unroll
            for (int i = 0; i < 4; i++) {
                const int f = tid + 256 * i;
                const int row = f >> 3, q = f & 7;
                const int gm = m0 + row;
                av[i] = (gm < M)
                    ? *reinterpret_cast<const float4*>(&A[(size_t)gm * DIM + q * 4])
                    : make_float4(0.f, 0.f, 0.f, 0.f);
            }
#pragma unroll
            for (int i = 0; i < 4; i++) {
                const int f = tid + 256 * i;
                const int row = f >> 3, q = f & 7;
                uint4 u = make_uint4(f2tf32(av[i].x), f2tf32(av[i].y),
                                     f2tf32(av[i].z), f2tf32(av[i].w));
                *reinterpret_cast<uint4*>(&As[row * ASTR + q * 4]) = u;
            }
            __syncthreads();
        }

        // ---- main loop over 8 K-chunks, double buffered ----
#pragma unroll 1
        for (int kc = 0; kc < 8; kc++) {
            const int buf = kc & 1;
            uint32_t* Ab = As + buf * A_WORDS;

            // prefetch next chunk into regs
            float4 av[4];
            if (kc < 7) {
#pragma unroll
                for (int i = 0; i < 4; i++) {
                    const int f = tid + 256 * i;
                    const int row = f >> 3, q = f & 7;
                    const int gm = m0 + row;
                    av[i] = (gm < M)
                        ? *reinterpret_cast<const float4*>(
                              &A[(size_t)gm * DIM + (kc + 1) * KC + q * 4])
                        : make_float4(0.f, 0.f, 0.f, 0.f);
                }
            }

            // compute on current buffer
#pragma unroll
            for (int k8 = 0; k8 < 4; k8++) {
                uint32_t a[2][4];
#pragma unroll
                for (int mf = 0; mf < 2; mf++) {
                    const int r0 = wm * 32 + mf * 16 + g;
                    const int kb = k8 * 8 + t;
                    a[mf][0] = Ab[r0 * ASTR + kb];
                    a[mf][1] = Ab[(r0 + 8) * ASTR + kb];
                    a[mf][2] = Ab[r0 * ASTR + kb + 4];
                    a[mf][3] = Ab[(r0 + 8) * ASTR + kb + 4];
                }
                uint32_t b[8][2];
#pragma unroll
                for (int nf = 0; nf < 8; nf++) {
                    const int col = wn * 64 + nf * 8 + g;
                    const int kr  = kc * KC + k8 * 8 + t;
                    b[nf][0] = Bs[kr * BSTR + col];
                    b[nf][1] = Bs[(kr + 4) * BSTR + col];
                }
#pragma unroll
                for (int mf = 0; mf < 2; mf++)
#pragma unroll
                    for (int nf = 0; nf < 8; nf++)
                        mma_tf32(c[mf][nf][0], c[mf][nf][1], c[mf][nf][2], c[mf][nf][3],
                                 a[mf][0], a[mf][1], a[mf][2], a[mf][3],
                                 b[nf][0], b[nf][1]);
            }

            // publish next chunk
            if (kc < 7) {
                const int nbuf = (kc + 1) & 1;
                uint32_t* An = As + nbuf * A_WORDS;
#pragma unroll
                for (int i = 0; i < 4; i++) {
                    const int f = tid + 256 * i;
                    const int row = f >> 3, q = f & 7;
                    uint4 u = make_uint4(f2tf32(av[i].x), f2tf32(av[i].y),
                                         f2tf32(av[i].z), f2tf32(av[i].w));
                    *reinterpret_cast<uint4*>(&An[row * ASTR + q * 4]) = u;
                }
                __syncthreads();
            }
        }

        // ---- epilogue: fp32 accum -> fp16 store ----
#pragma unroll
        for (int mf = 0; mf < 2; mf++) {
            const int r0 = m0 + wm * 32 + mf * 16 + g;
            const int r1 = r0 + 8;
#pragma unroll
            for (int nf = 0; nf < 8; nf++) {
                const int col = nhalf * BNH + wn * 64 + nf * 8 + t * 2;
                if (r0 < M) {
                    __half2 h = __floats2half2_rn(c[mf][nf][0], c[mf][nf][1]);
                    *reinterpret_cast<__half2*>(&C[(size_t)r0 * DIM + col]) = h;
                }
                if (r1 < M) {
                    __half2 h = __floats2half2_rn(c[mf][nf][2], c[mf][nf][3]);
                    *reinterpret_cast<__half2*>(&C[(size_t)r1 * DIM + col]) = h;
                }
            }
        }
    }
}

// ---------------------------------------------------------------------------
// Gather + uniform-average from fp16 source. One warp per row.
//   out[r] = (1/cnt) * sum_{l: id>0} src[id]   (cnt==0 -> all 32 slots, 1/32)
// EDGE=true:  src=g_x1, out=g_edge (fp32) + relu.
// EDGE=false: src=g_e1, out=d_out (fp32).
// ---------------------------------------------------------------------------
template <bool EDGE>
__global__ __launch_bounds__(256)
void gather_h(const int* __restrict__ idx, float* __restrict__ out_ext, int rows)
{
    const __half* __restrict__ src = EDGE ? g_x1 : g_e1;
    float* __restrict__ out        = EDGE ? g_edge : out_ext;

    const int wid  = threadIdx.x >> 5;
    const int lane = threadIdx.x & 31;
    const int r    = blockIdx.x * 8 + wid;
    if (r >= rows) return;

    const int myid = idx[(size_t)r * LW + lane];
    const unsigned bal = __ballot_sync(0xffffffffu, myid > 0);
    const int cnt = __popc(bal);
    const bool all = (cnt == 0);

    const uint4* __restrict__ sp = reinterpret_cast<const uint4*>(src);

    float acc[8];
#pragma unroll
    for (int j = 0; j < 8; j++) acc[j] = 0.f;

#pragma unroll
    for (int l = 0; l < LW; l++) {
        const int id = __shfl_sync(0xffffffffu, myid, l);
        if (all || id > 0) {
            // row = 256 halfs = 32 uint4; this lane's uint4 = 8 halfs
            const uint4 v = __ldg(&sp[(size_t)id * 32 + lane]);
            const float2 f0 = __half22float2(*reinterpret_cast<const __half2*>(&v.x));
            const float2 f1 = __half22float2(*reinterpret_cast<const __half2*>(&v.y));
            const float2 f2 = __half22float2(*reinterpret_cast<const __half2*>(&v.z));
            const float2 f3 = __half22float2(*reinterpret_cast<const __half2*>(&v.w));
            acc[0] += f0.x; acc[1] += f0.y;
            acc[2] += f1.x; acc[3] += f1.y;
            acc[4] += f2.x; acc[5] += f2.y;
            acc[6] += f3.x; acc[7] += f3.y;
        }
    }

    const float s = 1.f / (float)(cnt ? cnt : LW);
    float o[8];
#pragma unroll
    for (int j = 0; j < 8; j++) {
        o[j] = acc[j] * s;
        if (EDGE) o[j] = fmaxf(o[j], 0.f);
    }
    float* op = out + (size_t)r * DIM + lane * 8;
    *reinterpret_cast<float4*>(op + 0) = make_float4(o[0], o[1], o[2], o[3]);
    *reinterpret_cast<float4*>(op + 4) = make_float4(o[4], o[5], o[6], o[7]);
}

// ---------------------------------------------------------------------------
// Launch — kernel launches + one idempotent attribute set (capture-safe).
// ---------------------------------------------------------------------------
extern "C" void kernel_launch(void* const* d_in, const int* in_sizes, int n_in,
                              void* d_out, int out_size)
{
    const float* x    = (const float*)d_in[0];   // [N,256]
    const int*   seq  = (const int*)  d_in[1];   // [E,32]
    const int*   useq = (const int*)  d_in[2];   // [N,32]
    const float* W1   = (const float*)d_in[3];   // [256,256]
    const float* W2   = (const float*)d_in[4];   // [256,256]
    float*       out  = (float*)d_out;           // [N,256]

    int N = in_sizes[2] / LW;
    int E = in_sizes[1] / LW;
    if (N <= 0 || N > N_NODES) N = N_NODES;
    if (E <= 0 || E > N_EDGES) E = N_EDGES;

    cudaFuncSetAttribute(gemm_mma<true>,  cudaFuncAttributeMaxDynamicSharedMemorySize, GEMM_SMEM_BYTES);
    cudaFuncSetAttribute(gemm_mma<false>, cudaFuncAttributeMaxDynamicSharedMemorySize, GEMM_SMEM_BYTES);

    // 1) x1 = x @ W1   (fp16 out)
    gemm_mma<true><<<dim3(148, 2), 256, GEMM_SMEM_BYTES>>>(x, W1, N);

    // 2) edge = relu(gatherAvg(x1, seq))  (fp32)
    gather_h<true><<<(E + 7) / 8, 256>>>(seq, nullptr, E);

    // 3) e1 = edge @ W2  (fp16 out)
    gemm_mma<false><<<dim3(148, 2), 256, GEMM_SMEM_BYTES>>>(nullptr, W2, E);

    // 4) node = gatherAvg(e1, useq) -> d_out (fp32)
    gather_h<false><<<(N + 7) / 8, 256>>>(useq, out, N);
}

// round 12
// speedup vs baseline: 2.7925x; 1.1153x over previous
#include <cuda_runtime.h>
#include <cuda_fp16.h>
#include <cstdint>

// ===========================================================================
// HGNN layer (sm_103 generic target, GB300):
//   x1   = x @ W1      (mma.sync m16n8k16 fp16, fp32 accum, fp16 out) [N,256]
//   edge = relu(gatherAvg(x1, seq))     (fp16 in, fp16 out)           [E,256]
//   e1   = edge @ W2   (fp16 mma, fp16 out)                           [E,256]
//   node = gatherAvg(e1, useq)          (fp16 in, fp32 out)           [N,256]
// fp16 has the same 10-bit mantissa as tf32 -> same input precision, 2x rate.
// ===========================================================================

#define N_NODES 50000
#define N_EDGES 25000
#define DIM     256
#define LW      32

// Scratch (static __device__; no allocations anywhere).
__device__ __half g_x1[N_NODES * DIM];     // 25.6 MB
__device__ __half g_edge[N_EDGES * DIM];   // 12.8 MB
__device__ __half g_e1[N_EDGES * DIM];     // 12.8 MB

// ---------------------------------------------------------------------------
// helpers
// ---------------------------------------------------------------------------
__device__ __forceinline__ uint32_t pack_h2(float lo, float hi) {
    __half2 h = __floats2half2_rn(lo, hi);   // .x = lo (low 16 bits) = even k
    return *reinterpret_cast<uint32_t*>(&h);
}

__device__ __forceinline__ void mma_f16(float& c0, float& c1, float& c2, float& c3,
                                        uint32_t a0, uint32_t a1, uint32_t a2, uint32_t a3,
                                        uint32_t b0, uint32_t b1)
{
    asm volatile(
        "mma.sync.aligned.m16n8k16.row.col.f32.f16.f16.f32 "
        "{%0,%1,%2,%3}, {%4,%5,%6,%7}, {%8,%9}, {%0,%1,%2,%3};"
        : "+f"(c0), "+f"(c1), "+f"(c2), "+f"(c3)
        : "r"(a0), "r"(a1), "r"(a2), "r"(a3), "r"(b0), "r"(b1));
}

// ---------------------------------------------------------------------------
// Persistent fp16 tensor-core GEMM:
//   C[M,256](fp16) = A[M,256] @ W[256,256](fp32 -> fp16)
// Grid (148,2): blockIdx.y = 128-wide N half. W-half cached in smem once as
// packed half2 k-pairs, n-major: Bs[n][k2], NSTR=132 (conflict-free).
// A chunks (128 rows x 32 k) double-buffered as packed half2: As[row][k2],
// ASTR=20 (conflict-free). 8 warps = 4(M) x 2(N); warp tile 32x64;
// K = 8 chunks x 2 k16-steps.
// FIRST=true:  A = x (fp32 param), C = g_x1
// FIRST=false: A = g_edge (fp16),  C = g_e1
// ---------------------------------------------------------------------------
#define BM     128
#define BNH    128
#define KC     32
#define NSTR   132                        // B row stride (words)
#define ASTR   20                         // A row stride (words)
#define B_WORDS (128 * NSTR)              // 16896
#define A_WORDS (BM * ASTR)               // 2560
#define GEMM_SMEM_BYTES ((B_WORDS + 2 * A_WORDS) * 4)   // 88064 B

template <bool FIRST>
__global__ __launch_bounds__(256, 2)
void gemm_h(const float* __restrict__ Aext, const float* __restrict__ W, int M)
{
    __half* __restrict__ C = FIRST ? g_x1 : g_e1;

    extern __shared__ uint32_t sm[];
    uint32_t* Bs = sm;                       // [128 n][NSTR]
    uint32_t* As = sm + B_WORDS;             // [2][128][ASTR]

    const int tid  = threadIdx.x;
    const int lane = tid & 31;
    const int wid  = tid >> 5;
    const int wm   = wid >> 1;               // 0..3 -> rows wm*32
    const int wn   = wid & 1;                // 0..1 -> cols wn*64
    const int g    = lane >> 2;              // 0..7
    const int t    = lane & 3;               // 0..3
    const int nhalf = blockIdx.y;            // 0/1

    // ---- W half -> Bs (once): pack rows (2k2, 2k2+1) into half2 ----
    // 128 n x 128 k2 entries; thread handles 64 entries (16 iters x 4 n).
#pragma unroll 4
    for (int i = 0; i < 16; i++) {
        const int f  = tid + 256 * i;        // 0..4095
        const int n4 = f & 31;               // n quad
        const int k2 = f >> 5;               // 0..127
        const float* w0 = &W[(size_t)(2 * k2) * DIM + nhalf * BNH + n4 * 4];
        const float4 r0 = *reinterpret_cast<const float4*>(w0);
        const float4 r1 = *reinterpret_cast<const float4*>(w0 + DIM);
        Bs[(n4 * 4 + 0) * NSTR + k2] = pack_h2(r0.x, r1.x);
        Bs[(n4 * 4 + 1) * NSTR + k2] = pack_h2(r0.y, r1.y);
        Bs[(n4 * 4 + 2) * NSTR + k2] = pack_h2(r0.z, r1.z);
        Bs[(n4 * 4 + 3) * NSTR + k2] = pack_h2(r0.w, r1.w);
    }

    const int numTiles = (M + BM - 1) / BM;

    for (int tile = blockIdx.x; tile < numTiles; tile += gridDim.x) {
        const int m0 = tile * BM;

        float c[2][8][4];
#pragma unroll
        for (int mf = 0; mf < 2; mf++)
#pragma unroll
            for (int nf = 0; nf < 8; nf++)
#pragma unroll
                for (int j = 0; j < 4; j++) c[mf][nf][j] = 0.f;

        // ---- prologue: chunk 0 -> buf 0 ----
        __syncthreads();   // previous tile fully consumed before overwrite
        if (FIRST) {
#pragma unroll
            for (int i = 0; i < 4; i++) {
                const int f = tid + 256 * i;
                const int row = f >> 3, q = f & 7;
                const int gm = m0 + row;
                float4 v = make_float4(0.f, 0.f, 0.f, 0.f);
                if (gm < M)
                    v = *reinterpret_cast<const float4*>(&Aext[(size_t)gm * DIM + q * 4]);
                uint2 u = make_uint2(pack_h2(v.x, v.y), pack_h2(v.z, v.w));
                *reinterpret_cast<uint2*>(&As[row * ASTR + q * 2]) = u;
            }
        } else {
#pragma unroll
            for (int i = 0; i < 2; i++) {
                const int f = tid + 256 * i;
                const int row = f >> 2, q4 = f & 3;
                const int gm = m0 + row;
                uint4 v = make_uint4(0u, 0u, 0u, 0u);
                if (gm < M)
                    v = reinterpret_cast<const uint4*>(g_edge)[(size_t)gm * 32 + q4];
                *reinterpret_cast<uint4*>(&As[row * ASTR + q4 * 4]) = v;
            }
        }
        __syncthreads();

        // ---- main loop over 8 K-chunks, double buffered ----
#pragma unroll 1
        for (int kc = 0; kc < 8; kc++) {
            const int buf = kc & 1;
            uint32_t* Ab = As + buf * A_WORDS;

            // prefetch next chunk into regs
            float4 av[4];
            uint4  av2[2];
            if (kc < 7) {
                if (FIRST) {
#pragma unroll
                    for (int i = 0; i < 4; i++) {
                        const int f = tid + 256 * i;
                        const int row = f >> 3, q = f & 7;
                        const int gm = m0 + row;
                        av[i] = (gm < M)
                            ? *reinterpret_cast<const float4*>(
                                  &Aext[(size_t)gm * DIM + (kc + 1) * KC + q * 4])
                            : make_float4(0.f, 0.f, 0.f, 0.f);
                    }
                } else {
#pragma unroll
                    for (int i = 0; i < 2; i++) {
                        const int f = tid + 256 * i;
                        const int row = f >> 2, q4 = f & 3;
                        const int gm = m0 + row;
                        av2[i] = (gm < M)
                            ? reinterpret_cast<const uint4*>(g_edge)[(size_t)gm * 32 + (kc + 1) * 4 + q4]
                            : make_uint4(0u, 0u, 0u, 0u);
                    }
                }
            }

            // compute: 2 k16-steps on current buffer
#pragma unroll
            for (int s = 0; s < 2; s++) {
                uint32_t a[2][4];
#pragma unroll
                for (int mf = 0; mf < 2; mf++) {
                    const int r0 = wm * 32 + mf * 16 + g;
                    const int kb = s * 8 + t;
                    a[mf][0] = Ab[r0 * ASTR + kb];
                    a[mf][1] = Ab[(r0 + 8) * ASTR + kb];
                    a[mf][2] = Ab[r0 * ASTR + kb + 4];
                    a[mf][3] = Ab[(r0 + 8) * ASTR + kb + 4];
                }
                uint32_t b[8][2];
#pragma unroll
                for (int nf = 0; nf < 8; nf++) {
                    const int col = wn * 64 + nf * 8 + g;
                    const int kk  = kc * 16 + s * 8 + t;
                    b[nf][0] = Bs[col * NSTR + kk];
                    b[nf][1] = Bs[col * NSTR + kk + 4];
                }
#pragma unroll
                for (int mf = 0; mf < 2; mf++)
#pragma unroll
                    for (int nf = 0; nf < 8; nf++)
                        mma_f16(c[mf][nf][0], c[mf][nf][1], c[mf][nf][2], c[mf][nf][3],
                                a[mf][0], a[mf][1], a[mf][2], a[mf][3],
                                b[nf][0], b[nf][1]);
            }

            // publish next chunk
            if (kc < 7) {
                uint32_t* An = As + ((kc + 1) & 1) * A_WORDS;
                if (FIRST) {
#pragma unroll
                    for (int i = 0; i < 4; i++) {
                        const int f = tid + 256 * i;
                        const int row = f >> 3, q = f & 7;
                        uint2 u = make_uint2(pack_h2(av[i].x, av[i].y),
                                             pack_h2(av[i].z, av[i].w));
                        *reinterpret_cast<uint2*>(&An[row * ASTR + q * 2]) = u;
                    }
                } else {
#pragma unroll
                    for (int i = 0; i < 2; i++) {
                        const int f = tid + 256 * i;
                        const int row = f >> 2, q4 = f & 3;
                        *reinterpret_cast<uint4*>(&An[row * ASTR + q4 * 4]) = av2[i];
                    }
                }
                __syncthreads();
            }
        }

        // ---- epilogue: fp32 accum -> fp16 store ----
#pragma unroll
        for (int mf = 0; mf < 2; mf++) {
            const int r0 = m0 + wm * 32 + mf * 16 + g;
            const int r1 = r0 + 8;
#pragma unroll
            for (int nf = 0; nf < 8; nf++) {
                const int col = nhalf * BNH + wn * 64 + nf * 8 + t * 2;
                if (r0 < M) {
                    __half2 h = __floats2half2_rn(c[mf][nf][0], c[mf][nf][1]);
                    *reinterpret_cast<__half2*>(&C[(size_t)r0 * DIM + col]) = h;
                }
                if (r1 < M) {
                    __half2 h = __floats2half2_rn(c[mf][nf][2], c[mf][nf][3]);
                    *reinterpret_cast<__half2*>(&C[(size_t)r1 * DIM + col]) = h;
                }
            }
        }
    }
}

// ---------------------------------------------------------------------------
// Gather + uniform-average from fp16 source. One warp per row, fp32 accum.
//   out[r] = (1/cnt) * sum_{l: id>0} src[id]   (cnt==0 -> all 32 slots, 1/32)
// EDGE=true:  src=g_x1, out=g_edge (fp16) + relu.
// EDGE=false: src=g_e1, out=d_out (fp32).
// ---------------------------------------------------------------------------
template <bool EDGE>
__global__ __launch_bounds__(256)
void gather_h(const int* __restrict__ idx, float* __restrict__ out_ext, int rows)
{
    const __half* __restrict__ src = EDGE ? g_x1 : g_e1;

    const int wid  = threadIdx.x >> 5;
    const int lane = threadIdx.x & 31;
    const int r    = blockIdx.x * 8 + wid;
    if (r >= rows) return;

    const int myid = idx[(size_t)r * LW + lane];
    const unsigned bal = __ballot_sync(0xffffffffu, myid > 0);
    const int cnt = __popc(bal);
    const bool all = (cnt == 0);

    const uint4* __restrict__ sp = reinterpret_cast<const uint4*>(src);

    float acc[8];
#pragma unroll
    for (int j = 0; j < 8; j++) acc[j] = 0.f;

#pragma unroll
    for (int l = 0; l < LW; l++) {
        const int id = __shfl_sync(0xffffffffu, myid, l);
        if (all || id > 0) {
            const uint4 v = __ldg(&sp[(size_t)id * 32 + lane]);
            const float2 f0 = __half22float2(*reinterpret_cast<const __half2*>(&v.x));
            const float2 f1 = __half22float2(*reinterpret_cast<const __half2*>(&v.y));
            const float2 f2 = __half22float2(*reinterpret_cast<const __half2*>(&v.z));
            const float2 f3 = __half22float2(*reinterpret_cast<const __half2*>(&v.w));
            acc[0] += f0.x; acc[1] += f0.y;
            acc[2] += f1.x; acc[3] += f1.y;
            acc[4] += f2.x; acc[5] += f2.y;
            acc[6] += f3.x; acc[7] += f3.y;
        }
    }

    const float s = 1.f / (float)(cnt ? cnt : LW);
    float o[8];
#pragma unroll
    for (int j = 0; j < 8; j++) {
        o[j] = acc[j] * s;
        if (EDGE) o[j] = fmaxf(o[j], 0.f);
    }

    if (EDGE) {
        // fp16 output (relu'd), vectorized 16B store
        uint4 u;
        u.x = pack_h2(o[0], o[1]);
        u.y = pack_h2(o[2], o[3]);
        u.z = pack_h2(o[4], o[5]);
        u.w = pack_h2(o[6], o[7]);
        *reinterpret_cast<uint4*>(&g_edge[(size_t)r * DIM + lane * 8]) = u;
    } else {
        float* op = out_ext + (size_t)r * DIM + lane * 8;
        *reinterpret_cast<float4*>(op + 0) = make_float4(o[0], o[1], o[2], o[3]);
        *reinterpret_cast<float4*>(op + 4) = make_float4(o[4], o[5], o[6], o[7]);
    }
}

// ---------------------------------------------------------------------------
// Launch — kernel launches + idempotent attribute set (capture-safe).
// ---------------------------------------------------------------------------
extern "C" void kernel_launch(void* const* d_in, const int* in_sizes, int n_in,
                              void* d_out, int out_size)
{
    const float* x    = (const float*)d_in[0];   // [N,256]
    const int*   seq  = (const int*)  d_in[1];   // [E,32]
    const int*   useq = (const int*)  d_in[2];   // [N,32]
    const float* W1   = (const float*)d_in[3];   // [256,256]
    const float* W2   = (const float*)d_in[4];   // [256,256]
    float*       out  = (float*)d_out;           // [N,256]

    int N = in_sizes[2] / LW;
    int E = in_sizes[1] / LW;
    if (N <= 0 || N > N_NODES) N = N_NODES;
    if (E <= 0 || E > N_EDGES) E = N_EDGES;

    cudaFuncSetAttribute(gemm_h<true>,  cudaFuncAttributeMaxDynamicSharedMemorySize, GEMM_SMEM_BYTES);
    cudaFuncSetAttribute(gemm_h<false>, cudaFuncAttributeMaxDynamicSharedMemorySize, GEMM_SMEM_BYTES);

    // 1) x1 = x @ W1   (fp16 out)
    gemm_h<true><<<dim3(148, 2), 256, GEMM_SMEM_BYTES>>>(x, W1, N);

    // 2) edge = relu(gatherAvg(x1, seq))  (fp16 out)
    gather_h<true><<<(E + 7) / 8, 256>>>(seq, nullptr, E);

    // 3) e1 = edge @ W2  (fp16 out)
    gemm_h<false><<<dim3(148, 2), 256, GEMM_SMEM_BYTES>>>(nullptr, W2, E);

    // 4) node = gatherAvg(e1, useq) -> d_out (fp32)
    gather_h<false><<<(N + 7) / 8, 256>>>(useq, out, N);
}

// round 15
// speedup vs baseline: 2.9230x; 1.0467x over previous
#include <cuda_runtime.h>
#include <cuda_fp16.h>
#include <cstdint>

// ===========================================================================
// HGNN layer (sm_103 generic target, GB300):
//   x1   = x @ W1      (mma.sync m16n8k16 fp16 + ldmatrix)          [N,256]
//   edge = relu(gatherAvg(x1, seq))     (fp16 in, fp16 out)         [E,256]
//   e1   = edge @ W2   (fp16 mma)                                   [E,256]
//   node = gatherAvg(e1, useq)          (fp16 in, fp32 out)         [N,256]
// Gathers are at the LTS traffic cap (~13 TB/s) -> left untouched.
// GEMM fragment loads via ldmatrix.x4: 96 vs 384 smem ops per tile.
// ===========================================================================

#define N_NODES 50000
#define N_EDGES 25000
#define DIM     256
#define LW      32

__device__ __half g_x1[N_NODES * DIM];     // 25.6 MB
__device__ __half g_edge[N_EDGES * DIM];   // 12.8 MB
__device__ __half g_e1[N_EDGES * DIM];     // 12.8 MB

// ---------------------------------------------------------------------------
// helpers
// ---------------------------------------------------------------------------
__device__ __forceinline__ uint32_t pack_h2(float lo, float hi) {
    __half2 h = __floats2half2_rn(lo, hi);
    return *reinterpret_cast<uint32_t*>(&h);
}
__device__ __forceinline__ uint32_t smem_u32(const void* p) {
    uint32_t a;
    asm("{ .reg .u64 t; cvta.to.shared.u64 t, %1; cvt.u32.u64 %0, t; }" : "=r"(a) : "l"(p));
    return a;
}

__device__ __forceinline__ void mma_f16(float& c0, float& c1, float& c2, float& c3,
                                        uint32_t a0, uint32_t a1, uint32_t a2, uint32_t a3,
                                        uint32_t b0, uint32_t b1)
{
    asm volatile(
        "mma.sync.aligned.m16n8k16.row.col.f32.f16.f16.f32 "
        "{%0,%1,%2,%3}, {%4,%5,%6,%7}, {%8,%9}, {%0,%1,%2,%3};"
        : "+f"(c0), "+f"(c1), "+f"(c2), "+f"(c3)
        : "r"(a0), "r"(a1), "r"(a2), "r"(a3), "r"(b0), "r"(b1));
}

#define LDMX4(r0, r1, r2, r3, addr) \
    asm volatile("ldmatrix.sync.aligned.m8n8.x4.shared.b16 {%0,%1,%2,%3}, [%4];" \
        : "=r"(r0), "=r"(r1), "=r"(r2), "=r"(r3) : "r"(addr))

// ---------------------------------------------------------------------------
// Persistent fp16 tensor-core GEMM (ldmatrix fragments):
//   C[M,256](fp16) = A[M,256] @ W[256,256](fp32 -> fp16)
// Grid (148,2), 8 warps = 4(M) x 2(N), warp tile 32x64.
// Bs[n][k2] NSTR=132; As[2][row][k2] ASTR=20 (both ldmatrix conflict-free:
// A row-addr banks 20r%32 distinct 16B groups, B 132n%32 = 4n distinct).
// ---------------------------------------------------------------------------
#define BM     128
#define BNH    128
#define KC     32
#define NSTR   132
#define ASTR   20
#define B_WORDS (128 * NSTR)              // 16896
#define A_WORDS (BM * ASTR)               // 2560
#define GEMM_SMEM_BYTES ((B_WORDS + 2 * A_WORDS) * 4)   // 88064 B

template <bool FIRST>
__global__ __launch_bounds__(256, 2)
void gemm_h(const float* __restrict__ Aext, const float* __restrict__ W, int M)
{
    __half* __restrict__ C = FIRST ? g_x1 : g_e1;

    extern __shared__ uint32_t sm[];
    uint32_t* Bs = sm;                       // [128 n][NSTR]
    uint32_t* As = sm + B_WORDS;             // [2][128][ASTR]
    const uint32_t smB = smem_u32(sm);                 // B base (u32 shared addr)
    const uint32_t smA = smB + B_WORDS * 4;            // A base

    const int tid  = threadIdx.x;
    const int lane = tid & 31;
    const int wid  = tid >> 5;
    const int wm   = wid >> 1;
    const int wn   = wid & 1;
    const int nhalf = blockIdx.y;

    // ldmatrix lane-address components (precomputed, loop-invariant)
    // A: lanes 0-15 -> rows 0..15 (tiles a0/a1), lanes 16-31 same rows, k+8 halfs (a2/a3)
    const int a_row  = wm * 32 + (lane & 15);
    const int a_koff = (lane >> 4) * 4;                // words (= 8 halfs)
    // B: lanes 0-15 -> nf even (b0: k+0 / b1: k+4w), lanes 16-31 -> nf odd
    const int b_row  = wn * 64 + (lane >> 4) * 8 + (lane & 7);
    const int b_koff = ((lane >> 3) & 1) * 4;          // words

    // ---- W half -> Bs (once): pack rows (2k2, 2k2+1) into half2 ----
#pragma unroll 4
    for (int i = 0; i < 16; i++) {
        const int f  = tid + 256 * i;
        const int n4 = f & 31;
        const int k2 = f >> 5;
        const float* w0 = &W[(size_t)(2 * k2) * DIM + nhalf * BNH + n4 * 4];
        const float4 r0 = *reinterpret_cast<const float4*>(w0);
        const float4 r1 = *reinterpret_cast<const float4*>(w0 + DIM);
        Bs[(n4 * 4 + 0) * NSTR + k2] = pack_h2(r0.x, r1.x);
        Bs[(n4 * 4 + 1) * NSTR + k2] = pack_h2(r0.y, r1.y);
        Bs[(n4 * 4 + 2) * NSTR + k2] = pack_h2(r0.z, r1.z);
        Bs[(n4 * 4 + 3) * NSTR + k2] = pack_h2(r0.w, r1.w);
    }

    const int numTiles = (M + BM - 1) / BM;

    for (int tile = blockIdx.x; tile < numTiles; tile += gridDim.x) {
        const int m0 = tile * BM;

        float c[2][8][4];
#pragma unroll
        for (int mf = 0; mf < 2; mf++)
#pragma unroll
            for (int nf = 0; nf < 8; nf++)
#pragma unroll
                for (int j = 0; j < 4; j++) c[mf][nf][j] = 0.f;

        // ---- prologue: chunk 0 -> buf 0 ----
        __syncthreads();
        if (FIRST) {
#pragma unroll
            for (int i = 0; i < 4; i++) {
                const int f = tid + 256 * i;
                const int row = f >> 3, q = f & 7;
                const int gm = m0 + row;
                float4 v = make_float4(0.f, 0.f, 0.f, 0.f);
                if (gm < M)
                    v = *reinterpret_cast<const float4*>(&Aext[(size_t)gm * DIM + q * 4]);
                uint2 u = make_uint2(pack_h2(v.x, v.y), pack_h2(v.z, v.w));
                *reinterpret_cast<uint2*>(&As[row * ASTR + q * 2]) = u;
            }
        } else {
#pragma unroll
            for (int i = 0; i < 2; i++) {
                const int f = tid + 256 * i;
                const int row = f >> 2, q4 = f & 3;
                const int gm = m0 + row;
                uint4 v = make_uint4(0u, 0u, 0u, 0u);
                if (gm < M)
                    v = reinterpret_cast<const uint4*>(g_edge)[(size_t)gm * 32 + q4];
                *reinterpret_cast<uint4*>(&As[row * ASTR + q4 * 4]) = v;
            }
        }
        __syncthreads();

        // ---- main loop over 8 K-chunks, double buffered ----
#pragma unroll 1
        for (int kc = 0; kc < 8; kc++) {
            const uint32_t abase = smA + (uint32_t)(kc & 1) * (A_WORDS * 4);

            // prefetch next chunk into regs
            float4 av[4];
            uint4  av2[2];
            if (kc < 7) {
                if (FIRST) {
#pragma unroll
                    for (int i = 0; i < 4; i++) {
                        const int f = tid + 256 * i;
                        const int row = f >> 3, q = f & 7;
                        const int gm = m0 + row;
                        av[i] = (gm < M)
                            ? *reinterpret_cast<const float4*>(
                                  &Aext[(size_t)gm * DIM + (kc + 1) * KC + q * 4])
                            : make_float4(0.f, 0.f, 0.f, 0.f);
                    }
                } else {
#pragma unroll
                    for (int i = 0; i < 2; i++) {
                        const int f = tid + 256 * i;
                        const int row = f >> 2, q4 = f & 3;
                        const int gm = m0 + row;
                        av2[i] = (gm < M)
                            ? reinterpret_cast<const uint4*>(g_edge)[(size_t)gm * 32 + (kc + 1) * 4 + q4]
                            : make_uint4(0u, 0u, 0u, 0u);
                    }
                }
            }

            // compute: 2 k16-steps, fragments via ldmatrix.x4
#pragma unroll
            for (int s = 0; s < 2; s++) {
                uint32_t a[2][4];
#pragma unroll
                for (int mf = 0; mf < 2; mf++) {
                    const uint32_t addr = abase +
                        (uint32_t)(((a_row + mf * 16) * ASTR) + s * 8 + a_koff) * 4u;
                    LDMX4(a[mf][0], a[mf][1], a[mf][2], a[mf][3], addr);
                }
                uint32_t b[8][2];
#pragma unroll
                for (int nfp = 0; nfp < 4; nfp++) {
                    const uint32_t addr = smB +
                        (uint32_t)(((b_row + nfp * 16) * NSTR) + kc * 16 + s * 8 + b_koff) * 4u;
                    LDMX4(b[2 * nfp][0], b[2 * nfp][1],
                          b[2 * nfp + 1][0], b[2 * nfp + 1][1], addr);
                }
#pragma unroll
                for (int mf = 0; mf < 2; mf++)
#pragma unroll
                    for (int nf = 0; nf < 8; nf++)
                        mma_f16(c[mf][nf][0], c[mf][nf][1], c[mf][nf][2], c[mf][nf][3],
                                a[mf][0], a[mf][1], a[mf][2], a[mf][3],
                                b[nf][0], b[nf][1]);
            }

            // publish next chunk
            if (kc < 7) {
                uint32_t* An = As + ((kc + 1) & 1) * A_WORDS;
                if (FIRST) {
#pragma unroll
                    for (int i = 0; i < 4; i++) {
                        const int f = tid + 256 * i;
                        const int row = f >> 3, q = f & 7;
                        uint2 u = make_uint2(pack_h2(av[i].x, av[i].y),
                                             pack_h2(av[i].z, av[i].w));
                        *reinterpret_cast<uint2*>(&An[row * ASTR + q * 2]) = u;
                    }
                } else {
#pragma unroll
                    for (int i = 0; i < 2; i++) {
                        const int f = tid + 256 * i;
                        const int row = f >> 2, q4 = f & 3;
                        *reinterpret_cast<uint4*>(&An[row * ASTR + q4 * 4]) = av2[i];
                    }
                }
                __syncthreads();
            }
        }

        // ---- epilogue: fp32 accum -> fp16 store ----
#pragma unroll
        for (int mf = 0; mf < 2; mf++) {
            const int g = lane >> 2, t = lane & 3;
            const int r0 = m0 + wm * 32 + mf * 16 + g;
            const int r1 = r0 + 8;
#pragma unroll
            for (int nf = 0; nf < 8; nf++) {
                const int col = nhalf * BNH + wn * 64 + nf * 8 + t * 2;
                if (r0 < M) {
                    __half2 h = __floats2half2_rn(c[mf][nf][0], c[mf][nf][1]);
                    *reinterpret_cast<__half2*>(&C[(size_t)r0 * DIM + col]) = h;
                }
                if (r1 < M) {
                    __half2 h = __floats2half2_rn(c[mf][nf][2], c[mf][nf][3]);
                    *reinterpret_cast<__half2*>(&C[(size_t)r1 * DIM + col]) = h;
                }
            }
        }
    }
}

// ---------------------------------------------------------------------------
// Gather + uniform-average (UNCHANGED — at LTS traffic cap).
// ---------------------------------------------------------------------------
template <bool EDGE>
__global__ __launch_bounds__(256)
void gather_h(const int* __restrict__ idx, float* __restrict__ out_ext, int rows)
{
    const __half* __restrict__ src = EDGE ? g_x1 : g_e1;

    const int wid  = threadIdx.x >> 5;
    const int lane = threadIdx.x & 31;
    const int r    = blockIdx.x * 8 + wid;
    if (r >= rows) return;

    const int myid = idx[(size_t)r * LW + lane];
    const unsigned bal = __ballot_sync(0xffffffffu, myid > 0);
    const int cnt = __popc(bal);
    const bool all = (cnt == 0);

    const uint4* __restrict__ sp = reinterpret_cast<const uint4*>(src);

    float acc[8];
#pragma unroll
    for (int j = 0; j < 8; j++) acc[j] = 0.f;

#pragma unroll
    for (int l = 0; l < LW; l++) {
        const int id = __shfl_sync(0xffffffffu, myid, l);
        if (all || id > 0) {
            const uint4 v = __ldg(&sp[(size_t)id * 32 + lane]);
            const float2 f0 = __half22float2(*reinterpret_cast<const __half2*>(&v.x));
            const float2 f1 = __half22float2(*reinterpret_cast<const __half2*>(&v.y));
            const float2 f2 = __half22float2(*reinterpret_cast<const __half2*>(&v.z));
            const float2 f3 = __half22float2(*reinterpret_cast<const __half2*>(&v.w));
            acc[0] += f0.x; acc[1] += f0.y;
            acc[2] += f1.x; acc[3] += f1.y;
            acc[4] += f2.x; acc[5] += f2.y;
            acc[6] += f3.x; acc[7] += f3.y;
        }
    }

    const float s = 1.f / (float)(cnt ? cnt : LW);
    float o[8];
#pragma unroll
    for (int j = 0; j < 8; j++) {
        o[j] = acc[j] * s;
        if (EDGE) o[j] = fmaxf(o[j], 0.f);
    }

    if (EDGE) {
        uint4 u;
        u.x = pack_h2(o[0], o[1]);
        u.y = pack_h2(o[2], o[3]);
        u.z = pack_h2(o[4], o[5]);
        u.w = pack_h2(o[6], o[7]);
        *reinterpret_cast<uint4*>(&g_edge[(size_t)r * DIM + lane * 8]) = u;
    } else {
        float* op = out_ext + (size_t)r * DIM + lane * 8;
        *reinterpret_cast<float4*>(op + 0) = make_float4(o[0], o[1], o[2], o[3]);
        *reinterpret_cast<float4*>(op + 4) = make_float4(o[4], o[5], o[6], o[7]);
    }
}

// ---------------------------------------------------------------------------
// Launch
// ---------------------------------------------------------------------------
extern "C" void kernel_launch(void* const* d_in, const int* in_sizes, int n_in,
                              void* d_out, int out_size)
{
    const float* x    = (const float*)d_in[0];
    const int*   seq  = (const int*)  d_in[1];
    const int*   useq = (const int*)  d_in[2];
    const float* W1   = (const float*)d_in[3];
    const float* W2   = (const float*)d_in[4];
    float*       out  = (float*)d_out;

    int N = in_sizes[2] / LW;
    int E = in_sizes[1] / LW;
    if (N <= 0 || N > N_NODES) N = N_NODES;
    if (E <= 0 || E > N_EDGES) E = N_EDGES;

    cudaFuncSetAttribute(gemm_h<true>,  cudaFuncAttributeMaxDynamicSharedMemorySize, GEMM_SMEM_BYTES);
    cudaFuncSetAttribute(gemm_h<false>, cudaFuncAttributeMaxDynamicSharedMemorySize, GEMM_SMEM_BYTES);

    gemm_h<true><<<dim3(148, 2), 256, GEMM_SMEM_BYTES>>>(x, W1, N);
    gather_h<true><<<(E + 7) / 8, 256>>>(seq, nullptr, E);
    gemm_h<false><<<dim3(148, 2), 256, GEMM_SMEM_BYTES>>>(nullptr, W2, E);
    gather_h<false><<<(N + 7) / 8, 256>>>(useq, out, N);
}